// round 10
// baseline (speedup 1.0000x reference)
#include <cuda_runtime.h>
#include <cuda_fp16.h>
#include <stdint.h>

// NCA step via fp16 mma.sync.m16n8k16.
// R10: packed stencil stores (u32 STS via lane pairing) + coalesced epilogue
// through dxT staged in the dead h1 region. 4 CTAs/SM (53.2 KB smem).

#define HW   256
#define CH   16
#define TW   16
#define TH   8
#define NPIX 128
#define YPP  136      // u32 pitch for packed activation rows
#define XCS  184      // fp32 halo channel stride xs[16][10*18]
#define DP   20       // dxT fp32 pixel pitch

// u32-unit offsets
#define OFF_YS   0          // 24 pair-rows * 136 = 3264 ; h2 (16*136) aliases
#define OFF_H1   3264       // 32 * 136 = 4352 ; dxT (128*20=2560) aliases after GEMM2
#define OFF_XS   7616       // fp32 halo: 16*184 = 2944
#define OFF_WF1  10560      // 4*3*32*4 = 1536
#define OFF_WF2  12096      // 2*4*32*4 = 1024
#define OFF_WF3  13120      // 1*2*32*4 = 256
#define OFF_B1   13376
#define OFF_B2   13440
#define OFF_B3   13472
#define OFF_MS   13488
#define SMEM_U32 13616
#define SMEM_BYTES (SMEM_U32 * 4)

static_assert(OFF_H1  == OFF_YS + 24 * YPP, "ys");
static_assert(OFF_XS  == OFF_H1 + 32 * YPP, "h1");
static_assert(OFF_WF1 == OFF_XS + 16 * XCS, "xs");
static_assert(128 * DP <= 32 * YPP, "dxT fits in h1 region");
static_assert(OFF_MS + NPIX == SMEM_U32, "total");
static_assert(4 * SMEM_BYTES <= 227 * 1024, "4 CTA/SM");

__device__ __forceinline__ float tanh_fast(float v) {
    float y;
    asm("tanh.approx.f32 %0, %1;" : "=f"(y) : "f"(v));
    return y;
}
__device__ __forceinline__ uint32_t pack2h(float a, float b) {
    __half2 h = __floats2half2_rn(a, b);       // a -> low half
    return *(uint32_t*)&h;
}
__device__ __forceinline__ uint32_t lows2(uint32_t x, uint32_t y)  { return __byte_perm(x, y, 0x5410); }
__device__ __forceinline__ uint32_t highs2(uint32_t x, uint32_t y) { return __byte_perm(x, y, 0x7632); }

__device__ __forceinline__ void mma_f16(float& c0, float& c1, float& c2, float& c3,
                                        uint32_t a0, uint32_t a1, uint32_t a2, uint32_t a3,
                                        uint32_t b0, uint32_t b1)
{
    asm volatile(
        "mma.sync.aligned.m16n8k16.row.col.f32.f16.f16.f32 "
        "{%0,%1,%2,%3},{%4,%5,%6,%7},{%8,%9},{%0,%1,%2,%3};"
        : "+f"(c0), "+f"(c1), "+f"(c2), "+f"(c3)
        : "r"(a0), "r"(a1), "r"(a2), "r"(a3), "r"(b0), "r"(b1));
}

// Stage weights [K=KT*16][D] (fp32, d-contiguous) into fragment order.
template<int D, int KT>
__device__ __forceinline__ void stage_w(const float* __restrict__ w, uint32_t* dst, int tid)
{
    #pragma unroll 1
    for (int p = tid; p < 8 * KT * D; p += 256) {
        int kp = p / D, d = p % D;
        int kt = kp >> 3, kl = kp & 7;
        int t = kl & 3, khalf = kl >> 2;
        int dt = d >> 4, g = d & 7, rhi = (d >> 3) & 1;
        int reg = khalf * 2 + rhi, lane = g * 4 + t;
        float lo = w[(2 * kp) * D + d];
        float hi = w[(2 * kp + 1) * D + d];
        dst[((dt * KT + kt) * 32 + lane) * 4 + reg] = pack2h(lo, hi);
    }
}

__global__ __launch_bounds__(256, 4)
void nca_step_kernel(const float* __restrict__ x,
                     const float* __restrict__ w1, const float* __restrict__ b1,
                     const float* __restrict__ w2, const float* __restrict__ b2,
                     const float* __restrict__ w3, const float* __restrict__ b3,
                     const uint32_t* __restrict__ mask,
                     float* __restrict__ out)
{
    extern __shared__ uint32_t smu[];
    uint32_t* ysU = smu + OFF_YS;
    uint32_t* h2U = smu + OFF_YS;            // alias: ys dead after GEMM1 barrier
    uint32_t* h1U = smu + OFF_H1;
    float*    dxT = (float*)(smu + OFF_H1);  // alias: h1 dead after GEMM2 barrier
    float*    xs  = (float*)(smu + OFF_XS);
    uint32_t* wf1 = smu + OFF_WF1;
    uint32_t* wf2 = smu + OFF_WF2;
    uint32_t* wf3 = smu + OFF_WF3;
    float*    b1s = (float*)(smu + OFF_B1);
    float*    b2s = (float*)(smu + OFF_B2);
    float*    b3s = (float*)(smu + OFF_B3);
    float*    ms  = (float*)(smu + OFF_MS);

    const int tid = threadIdx.x;
    const int bx = blockIdx.x, by = blockIdx.y, bb = blockIdx.z;
    const int y0 = by * TH, x0 = bx * TW;

    // ---------------- phase 0: weight fragments / biases / mask / halo ----------------
    stage_w<64, 3>(w1, wf1, tid);
    stage_w<32, 4>(w2, wf2, tid);
    stage_w<16, 2>(w3, wf3, tid);

    if (tid < 64)       b1s[tid] = b1[tid];
    else if (tid < 96)  b2s[tid - 64] = b2[tid - 64];
    else if (tid < 112) b3s[tid - 96] = b3[tid - 96];

    if (tid < NPIX) {
        int py = tid >> 4, xx = tid & 15;
        uint32_t w = mask[((size_t)bb * HW + (y0 + py)) * HW + (x0 + xx)];
        ms[tid] = (w != 0u) ? 1.f : 0.f;
    }

    {   // halo 10x18, channel-major fp32, zero-pad outside image
        const float* xb = x + (size_t)bb * HW * HW * CH;
        const int gy0 = y0 - 1, gx0 = x0 - 1;
        for (int i = tid; i < 10 * 18 * 4; i += 256) {
            int q = i & 3, pix = i >> 2;
            int r = pix / 18, cc = pix - r * 18;
            int gr = gy0 + r, gc = gx0 + cc;
            float4 v = make_float4(0.f, 0.f, 0.f, 0.f);
            if ((unsigned)gr < HW && (unsigned)gc < HW)
                v = *(const float4*)&xb[((size_t)gr * HW + gc) * CH + q * 4];
            int base = r * 18 + cc;
            xs[(4 * q + 0) * XCS + base] = v.x;
            xs[(4 * q + 1) * XCS + base] = v.y;
            xs[(4 * q + 2) * XCS + base] = v.z;
            xs[(4 * q + 3) * XCS + base] = v.w;
        }
    }
    __syncthreads();

    // ---------------- phase 1: stencil -> ys (fp16 k-pair packed, u32 stores) ----------------
    {
        // thread: c = tid>>4, xx = tid&15. Lane pair (c even <-> c odd) via shfl_xor(16).
        // Features of channels (2m, 2m+1) pack into pair-rows 3m, 3m+1, 3m+2:
        //   row 3m   = (I_e , gx_e)   written by even-c thread
        //   row 3m+1 = (gy_e, I_o )   written by even-c thread (I_o via shuffle)
        //   row 3m+2 = (gx_o, gy_o)   written by odd-c thread
        const int c = tid >> 4, xx = tid & 15;
        const bool ceven = (c & 1) == 0;
        const int m = c >> 1;
        const float* xc = xs + c * XCS;
        float r0a = xc[xx],      r0b = xc[xx + 1],      r0c = xc[xx + 2];
        float r1a = xc[18 + xx], r1b = xc[18 + xx + 1], r1c = xc[18 + xx + 2];
        #pragma unroll
        for (int py = 0; py < TH; py++) {
            const float* row2 = xc + (py + 2) * 18 + xx;
            float r2a = row2[0], r2b = row2[1], r2c = row2[2];
            float gx = ((r0c - r0a) + 2.f * (r1c - r1a) + (r2c - r2a)) * 0.125f;
            float gy = ((r2a - r0a) + 2.f * (r2b - r0b) + (r2c - r0c)) * 0.125f;
            float I  = r1b;
            float Iot = __shfl_xor_sync(0xffffffffu, I, 16);
            int p = py * 16 + xx;
            if (ceven) {
                ysU[(3 * m + 0) * YPP + p] = pack2h(I, gx);
                ysU[(3 * m + 1) * YPP + p] = pack2h(gy, Iot);
            } else {
                ysU[(3 * m + 2) * YPP + p] = pack2h(gx, gy);
            }
            r0a = r1a; r0b = r1b; r0c = r1c;
            r1a = r2a; r1b = r2b; r1c = r2c;
        }
    }
    __syncthreads();

    const int lane = tid & 31, warp = tid >> 5;
    const int g = lane >> 2, t = lane & 3;
    const bool geven = (g & 1) == 0;

    // ---------------- phase 2: GEMM1 h1[64][128] = tanh(W1^T @ ys + b1) ----------------
    {
        const int dt = warp & 3, pb = (warp >> 2) * 64;
        const int d0 = dt * 16;
        uint4 A[3];
        #pragma unroll
        for (int kt = 0; kt < 3; kt++)
            A[kt] = *(const uint4*)&wf1[((dt * 3 + kt) * 32 + lane) * 4];
        const float bl = b1s[d0 + g], bh = b1s[d0 + g + 8];
        const int jlo = (d0 + g) >> 1;
        const int jhi = (d0 + g + 7) >> 1;
        #pragma unroll
        for (int nt = 0; nt < 8; nt++) {
            const int px0 = pb + nt * 8;
            float c0 = bl, c1 = bl, c2 = bh, c3 = bh;
            #pragma unroll
            for (int kt = 0; kt < 3; kt++) {
                uint32_t bv0 = ysU[(8 * kt + t) * YPP + px0 + g];
                uint32_t bv1 = ysU[(8 * kt + t + 4) * YPP + px0 + g];
                mma_f16(c0, c1, c2, c3, A[kt].x, A[kt].y, A[kt].z, A[kt].w, bv0, bv1);
            }
            uint32_t myL = pack2h(tanh_fast(c0), tanh_fast(c1));
            uint32_t myH = pack2h(tanh_fast(c2), tanh_fast(c3));
            uint32_t otL = __shfl_xor_sync(0xffffffffu, myL, 4);
            uint32_t otH = __shfl_xor_sync(0xffffffffu, myH, 4);
            if (geven) {
                h1U[jlo * YPP + px0 + 2 * t]     = lows2(myL, otL);
                h1U[jlo * YPP + px0 + 2 * t + 1] = highs2(myL, otL);
            } else {
                h1U[jhi * YPP + px0 + 2 * t]     = lows2(otH, myH);
                h1U[jhi * YPP + px0 + 2 * t + 1] = highs2(otH, myH);
            }
        }
    }
    __syncthreads();   // ys reads done -> h2 may overwrite aliased region

    // ---------------- phase 3: GEMM2 h2[32][128] = tanh(W2^T @ h1 + b2) ----------------
    {
        const int dt = warp & 1, pb = (warp >> 1) * 32;
        const int d0 = dt * 16;
        uint4 A[4];
        #pragma unroll
        for (int kt = 0; kt < 4; kt++)
            A[kt] = *(const uint4*)&wf2[((dt * 4 + kt) * 32 + lane) * 4];
        const float bl = b2s[d0 + g], bh = b2s[d0 + g + 8];
        const int jlo = (d0 + g) >> 1;
        const int jhi = (d0 + g + 7) >> 1;
        #pragma unroll
        for (int nt = 0; nt < 4; nt++) {
            const int px0 = pb + nt * 8;
            float c0 = bl, c1 = bl, c2 = bh, c3 = bh;
            #pragma unroll
            for (int kt = 0; kt < 4; kt++) {
                uint32_t bv0 = h1U[(8 * kt + t) * YPP + px0 + g];
                uint32_t bv1 = h1U[(8 * kt + t + 4) * YPP + px0 + g];
                mma_f16(c0, c1, c2, c3, A[kt].x, A[kt].y, A[kt].z, A[kt].w, bv0, bv1);
            }
            uint32_t myL = pack2h(tanh_fast(c0), tanh_fast(c1));
            uint32_t myH = pack2h(tanh_fast(c2), tanh_fast(c3));
            uint32_t otL = __shfl_xor_sync(0xffffffffu, myL, 4);
            uint32_t otH = __shfl_xor_sync(0xffffffffu, myH, 4);
            if (geven) {
                h2U[jlo * YPP + px0 + 2 * t]     = lows2(myL, otL);
                h2U[jlo * YPP + px0 + 2 * t + 1] = highs2(myL, otL);
            } else {
                h2U[jhi * YPP + px0 + 2 * t]     = lows2(otH, myH);
                h2U[jhi * YPP + px0 + 2 * t + 1] = highs2(otH, myH);
            }
        }
    }
    __syncthreads();   // h1 reads done -> dxT may overwrite aliased region

    // ---------------- phase 4: GEMM3 dx = W3^T @ h2 + b3 -> dxT[px][16] ----------------
    {
        uint4 A[2];
        #pragma unroll
        for (int kt = 0; kt < 2; kt++)
            A[kt] = *(const uint4*)&wf3[(kt * 32 + lane) * 4];
        const float bl = b3s[g], bh = b3s[g + 8];
        #pragma unroll
        for (int nt = 0; nt < 2; nt++) {
            const int px0 = warp * 16 + nt * 8;
            float c0 = bl, c1 = bl, c2 = bh, c3 = bh;
            #pragma unroll
            for (int kt = 0; kt < 2; kt++) {
                uint32_t bv0 = h2U[(8 * kt + t) * YPP + px0 + g];
                uint32_t bv1 = h2U[(8 * kt + t + 4) * YPP + px0 + g];
                mma_f16(c0, c1, c2, c3, A[kt].x, A[kt].y, A[kt].z, A[kt].w, bv0, bv1);
            }
            const int p0 = px0 + 2 * t, p1 = p0 + 1;
            dxT[p0 * DP + g]     = c0;
            dxT[p1 * DP + g]     = c1;
            dxT[p0 * DP + g + 8] = c2;
            dxT[p1 * DP + g + 8] = c3;
        }
    }
    __syncthreads();

    // ---------------- phase 5: out = x + dx*mask (coalesced STG.128) ----------------
    {
        const int px = tid >> 1;          // 0..127
        const int h = (tid & 1) * 8;      // channel half
        const int py = px >> 4, xx = px & 15;
        const float m = ms[px];
        const float4 d0 = *(const float4*)&dxT[px * DP + h];
        const float4 d1 = *(const float4*)&dxT[px * DP + h + 4];
        const int hb = (py + 1) * 18 + (xx + 1);
        float* o = out + (((size_t)bb * HW + (y0 + py)) * HW + (x0 + xx)) * CH + h;
        float4 r0, r1;
        r0.x = xs[(h + 0) * XCS + hb] + d0.x * m;
        r0.y = xs[(h + 1) * XCS + hb] + d0.y * m;
        r0.z = xs[(h + 2) * XCS + hb] + d0.z * m;
        r0.w = xs[(h + 3) * XCS + hb] + d0.w * m;
        r1.x = xs[(h + 4) * XCS + hb] + d1.x * m;
        r1.y = xs[(h + 5) * XCS + hb] + d1.y * m;
        r1.z = xs[(h + 6) * XCS + hb] + d1.z * m;
        r1.w = xs[(h + 7) * XCS + hb] + d1.w * m;
        *(float4*)&o[0] = r0;
        *(float4*)&o[4] = r1;
    }
}

extern "C" void kernel_launch(void* const* d_in, const int* in_sizes, int n_in,
                              void* d_out, int out_size)
{
    const float* x  = (const float*)d_in[0];
    const float* w1 = (const float*)d_in[1];
    const float* b1 = (const float*)d_in[2];
    const float* w2 = (const float*)d_in[3];
    const float* b2 = (const float*)d_in[4];
    const float* w3 = (const float*)d_in[5];
    const float* b3 = (const float*)d_in[6];
    const uint32_t* mask = (const uint32_t*)d_in[7];
    float* out = (float*)d_out;

    cudaFuncSetAttribute(nca_step_kernel,
                         cudaFuncAttributeMaxDynamicSharedMemorySize, SMEM_BYTES);
    dim3 grid(HW / TW, HW / TH, 16);
    nca_step_kernel<<<grid, 256, SMEM_BYTES>>>(x, w1, b1, w2, b2, w3, b3, mask, out);
}

// round 11
// speedup vs baseline: 1.1466x; 1.1466x over previous
#include <cuda_runtime.h>
#include <cuda_fp16.h>
#include <stdint.h>

// NCA step via fp16 mma.sync.m16n8k16, warp-standalone chain.
// Each warp owns 16 px; GEMM1->GEMM2->GEMM3 entirely in registers using
// movmatrix.m8n8.trans to convert C fragments to next-stage B fragments.
// No h1/h2 smem buffers; 2 barriers total. 37 KB smem, 4 CTAs/SM.

#define HW   256
#define CH   16
#define TW   16
#define TH   8
#define NPIX 128
#define YPP  136      // u32 pitch for packed ys rows (conflict-free)
#define XCS  184      // fp32 halo channel stride xs[16][10*18]

// u32-unit offsets
#define OFF_YS   0          // 24 pair-rows * 136 = 3264
#define OFF_XS   3264       // fp32 halo: 16*184 = 2944
#define OFF_WF1  6208       // 4*3*32*4 = 1536
#define OFF_WF2  7744       // 2*4*32*4 = 1024
#define OFF_WF3  8768       // 1*2*32*4 = 256
#define OFF_B1   9024
#define OFF_B2   9088
#define OFF_B3   9120
#define OFF_MS   9136
#define SMEM_U32 9264
#define SMEM_BYTES (SMEM_U32 * 4)

static_assert(OFF_XS  == OFF_YS + 24 * YPP, "ys");
static_assert(OFF_WF1 == OFF_XS + 16 * XCS, "xs");
static_assert(OFF_WF2 == OFF_WF1 + 1536, "wf1");
static_assert(OFF_WF3 == OFF_WF2 + 1024, "wf2");
static_assert(OFF_B1  == OFF_WF3 + 256, "wf3");
static_assert(OFF_MS + NPIX == SMEM_U32, "total");
static_assert(4 * SMEM_BYTES <= 227 * 1024, "4 CTA/SM");

__device__ __forceinline__ float tanh_fast(float v) {
    float y;
    asm("tanh.approx.f32 %0, %1;" : "=f"(y) : "f"(v));
    return y;
}
__device__ __forceinline__ uint32_t pack2h(float a, float b) {
    __half2 h = __floats2half2_rn(a, b);       // a -> low half
    return *(uint32_t*)&h;
}
__device__ __forceinline__ uint32_t movm_t(uint32_t s) {
    uint32_t d;
    asm("movmatrix.sync.aligned.m8n8.trans.b16 %0, %1;" : "=r"(d) : "r"(s));
    return d;
}
__device__ __forceinline__ void mma_f16(float& c0, float& c1, float& c2, float& c3,
                                        uint32_t a0, uint32_t a1, uint32_t a2, uint32_t a3,
                                        uint32_t b0, uint32_t b1)
{
    asm volatile(
        "mma.sync.aligned.m16n8k16.row.col.f32.f16.f16.f32 "
        "{%0,%1,%2,%3},{%4,%5,%6,%7},{%8,%9},{%0,%1,%2,%3};"
        : "+f"(c0), "+f"(c1), "+f"(c2), "+f"(c3)
        : "r"(a0), "r"(a1), "r"(a2), "r"(a3), "r"(b0), "r"(b1));
}

// Stage weights [K=KT*16][D] (fp32, d-contiguous) into fragment order.
template<int D, int KT>
__device__ __forceinline__ void stage_w(const float* __restrict__ w, uint32_t* dst, int tid)
{
    #pragma unroll 1
    for (int p = tid; p < 8 * KT * D; p += 256) {
        int kp = p / D, d = p % D;
        int kt = kp >> 3, kl = kp & 7;
        int t = kl & 3, khalf = kl >> 2;
        int dt = d >> 4, g = d & 7, rhi = (d >> 3) & 1;
        int reg = khalf * 2 + rhi, lane = g * 4 + t;
        float lo = w[(2 * kp) * D + d];
        float hi = w[(2 * kp + 1) * D + d];
        dst[((dt * KT + kt) * 32 + lane) * 4 + reg] = pack2h(lo, hi);
    }
}

__global__ __launch_bounds__(256, 4)
void nca_step_kernel(const float* __restrict__ x,
                     const float* __restrict__ w1, const float* __restrict__ b1,
                     const float* __restrict__ w2, const float* __restrict__ b2,
                     const float* __restrict__ w3, const float* __restrict__ b3,
                     const uint32_t* __restrict__ mask,
                     float* __restrict__ out)
{
    extern __shared__ uint32_t smu[];
    uint32_t* ysU = smu + OFF_YS;
    float*    xs  = (float*)(smu + OFF_XS);
    uint32_t* wf1 = smu + OFF_WF1;
    uint32_t* wf2 = smu + OFF_WF2;
    uint32_t* wf3 = smu + OFF_WF3;
    float*    b1s = (float*)(smu + OFF_B1);
    float*    b2s = (float*)(smu + OFF_B2);
    float*    b3s = (float*)(smu + OFF_B3);
    float*    ms  = (float*)(smu + OFF_MS);

    const int tid = threadIdx.x;
    const int bx = blockIdx.x, by = blockIdx.y, bb = blockIdx.z;
    const int y0 = by * TH, x0 = bx * TW;

    // ---------------- phase 0: weight fragments / biases / mask / halo ----------------
    stage_w<64, 3>(w1, wf1, tid);
    stage_w<32, 4>(w2, wf2, tid);
    stage_w<16, 2>(w3, wf3, tid);

    if (tid < 64)       b1s[tid] = b1[tid];
    else if (tid < 96)  b2s[tid - 64] = b2[tid - 64];
    else if (tid < 112) b3s[tid - 96] = b3[tid - 96];

    if (tid < NPIX) {
        int py = tid >> 4, xx = tid & 15;
        uint32_t w = mask[((size_t)bb * HW + (y0 + py)) * HW + (x0 + xx)];
        ms[tid] = (w != 0u) ? 1.f : 0.f;
    }

    {   // halo 10x18, channel-major fp32, zero-pad outside image
        const float* xb = x + (size_t)bb * HW * HW * CH;
        const int gy0 = y0 - 1, gx0 = x0 - 1;
        for (int i = tid; i < 10 * 18 * 4; i += 256) {
            int q = i & 3, pix = i >> 2;
            int r = pix / 18, cc = pix - r * 18;
            int gr = gy0 + r, gc = gx0 + cc;
            float4 v = make_float4(0.f, 0.f, 0.f, 0.f);
            if ((unsigned)gr < HW && (unsigned)gc < HW)
                v = *(const float4*)&xb[((size_t)gr * HW + gc) * CH + q * 4];
            int base = r * 18 + cc;
            xs[(4 * q + 0) * XCS + base] = v.x;
            xs[(4 * q + 1) * XCS + base] = v.y;
            xs[(4 * q + 2) * XCS + base] = v.z;
            xs[(4 * q + 3) * XCS + base] = v.w;
        }
    }
    __syncthreads();

    // ---------------- phase 1: stencil -> ys (fp16 k-pair packed halves) ----------------
    {
        const int c = tid >> 4, xx = tid & 15;
        const float* xc = xs + c * XCS;
        __half* ysH = (__half*)ysU;
        float r0a = xc[xx],      r0b = xc[xx + 1],      r0c = xc[xx + 2];
        float r1a = xc[18 + xx], r1b = xc[18 + xx + 1], r1c = xc[18 + xx + 2];
        const int f0 = 3 * c, f1 = 3 * c + 1, f2 = 3 * c + 2;
        __half* pI = ysH + (f0 >> 1) * (2 * YPP) + (f0 & 1);
        __half* pX = ysH + (f1 >> 1) * (2 * YPP) + (f1 & 1);
        __half* pY = ysH + (f2 >> 1) * (2 * YPP) + (f2 & 1);
        #pragma unroll
        for (int py = 0; py < TH; py++) {
            const float* row2 = xc + (py + 2) * 18 + xx;
            float r2a = row2[0], r2b = row2[1], r2c = row2[2];
            float gx = ((r0c - r0a) + 2.f * (r1c - r1a) + (r2c - r2a)) * 0.125f;
            float gy = ((r2a - r0a) + 2.f * (r2b - r0b) + (r2c - r0c)) * 0.125f;
            int p2 = (py * 16 + xx) * 2;
            pI[p2] = __float2half_rn(r1b);
            pX[p2] = __float2half_rn(gx);
            pY[p2] = __float2half_rn(gy);
            r0a = r1a; r0b = r1b; r0c = r1c;
            r1a = r2a; r1b = r2b; r1c = r2c;
        }
    }
    __syncthreads();

    // ---------------- warp-standalone GEMM chain: 16 px per warp ----------------
    const int lane = tid & 31, warp = tid >> 5;
    const int g = lane >> 2, t = lane & 3;
    const int px0 = warp * 16;

    // B fragments of ys for this warp's 16 px: [kt=3][nt=2][2]
    uint32_t ysB[3][2][2];
    #pragma unroll
    for (int kt = 0; kt < 3; kt++)
        #pragma unroll
        for (int nt = 0; nt < 2; nt++) {
            ysB[kt][nt][0] = ysU[(8 * kt + t) * YPP + px0 + nt * 8 + g];
            ysB[kt][nt][1] = ysU[(8 * kt + t + 4) * YPP + px0 + nt * 8 + g];
        }

    // GEMM1: h1 = tanh(W1^T @ ys + b1) -> B fragments h1B[kt=4][nt=2][2]
    uint32_t h1B[4][2][2];
    #pragma unroll
    for (int mt = 0; mt < 4; mt++) {
        uint4 A0 = *(const uint4*)&wf1[((mt * 3 + 0) * 32 + lane) * 4];
        uint4 A1 = *(const uint4*)&wf1[((mt * 3 + 1) * 32 + lane) * 4];
        uint4 A2 = *(const uint4*)&wf1[((mt * 3 + 2) * 32 + lane) * 4];
        const float bl = b1s[mt * 16 + g], bh = b1s[mt * 16 + g + 8];
        #pragma unroll
        for (int nt = 0; nt < 2; nt++) {
            float c0 = bl, c1 = bl, c2 = bh, c3 = bh;
            mma_f16(c0, c1, c2, c3, A0.x, A0.y, A0.z, A0.w, ysB[0][nt][0], ysB[0][nt][1]);
            mma_f16(c0, c1, c2, c3, A1.x, A1.y, A1.z, A1.w, ysB[1][nt][0], ysB[1][nt][1]);
            mma_f16(c0, c1, c2, c3, A2.x, A2.y, A2.z, A2.w, ysB[2][nt][0], ysB[2][nt][1]);
            h1B[mt][nt][0] = movm_t(pack2h(tanh_fast(c0), tanh_fast(c1)));
            h1B[mt][nt][1] = movm_t(pack2h(tanh_fast(c2), tanh_fast(c3)));
        }
    }

    // GEMM2: h2 = tanh(W2^T @ h1 + b2) -> B fragments h2B[kt=2][nt=2][2]
    uint32_t h2B[2][2][2];
    #pragma unroll
    for (int mt = 0; mt < 2; mt++) {
        uint4 A0 = *(const uint4*)&wf2[((mt * 4 + 0) * 32 + lane) * 4];
        uint4 A1 = *(const uint4*)&wf2[((mt * 4 + 1) * 32 + lane) * 4];
        uint4 A2 = *(const uint4*)&wf2[((mt * 4 + 2) * 32 + lane) * 4];
        uint4 A3 = *(const uint4*)&wf2[((mt * 4 + 3) * 32 + lane) * 4];
        const float bl = b2s[mt * 16 + g], bh = b2s[mt * 16 + g + 8];
        #pragma unroll
        for (int nt = 0; nt < 2; nt++) {
            float c0 = bl, c1 = bl, c2 = bh, c3 = bh;
            mma_f16(c0, c1, c2, c3, A0.x, A0.y, A0.z, A0.w, h1B[0][nt][0], h1B[0][nt][1]);
            mma_f16(c0, c1, c2, c3, A1.x, A1.y, A1.z, A1.w, h1B[1][nt][0], h1B[1][nt][1]);
            mma_f16(c0, c1, c2, c3, A2.x, A2.y, A2.z, A2.w, h1B[2][nt][0], h1B[2][nt][1]);
            mma_f16(c0, c1, c2, c3, A3.x, A3.y, A3.z, A3.w, h1B[3][nt][0], h1B[3][nt][1]);
            h2B[mt][nt][0] = movm_t(pack2h(tanh_fast(c0), tanh_fast(c1)));
            h2B[mt][nt][1] = movm_t(pack2h(tanh_fast(c2), tanh_fast(c3)));
        }
    }

    // GEMM3: dx = W3^T @ h2 + b3, fused epilogue (out = x + dx*mask)
    {
        uint4 A0 = *(const uint4*)&wf3[(0 * 32 + lane) * 4];
        uint4 A1 = *(const uint4*)&wf3[(1 * 32 + lane) * 4];
        const float bl = b3s[g], bh = b3s[g + 8];
        float* ob = out + (((size_t)bb * HW + y0) * HW + x0) * CH;
        #pragma unroll
        for (int nt = 0; nt < 2; nt++) {
            float c0 = bl, c1 = bl, c2 = bh, c3 = bh;
            mma_f16(c0, c1, c2, c3, A0.x, A0.y, A0.z, A0.w, h2B[0][nt][0], h2B[0][nt][1]);
            mma_f16(c0, c1, c2, c3, A1.x, A1.y, A1.z, A1.w, h2B[1][nt][0], h2B[1][nt][1]);
            const int p0 = px0 + nt * 8 + 2 * t, p1 = p0 + 1;
            const float m0 = ms[p0], m1 = ms[p1];
            const int py0 = p0 >> 4, xx0 = p0 & 15;
            const int py1 = p1 >> 4, xx1 = p1 & 15;
            const int hb0 = (py0 + 1) * 18 + (xx0 + 1);
            const int hb1 = (py1 + 1) * 18 + (xx1 + 1);
            float* o0 = ob + ((size_t)py0 * HW + xx0) * CH;
            float* o1 = ob + ((size_t)py1 * HW + xx1) * CH;
            o0[g]     = xs[g * XCS + hb0]       + c0 * m0;
            o1[g]     = xs[g * XCS + hb1]       + c1 * m1;
            o0[g + 8] = xs[(g + 8) * XCS + hb0] + c2 * m0;
            o1[g + 8] = xs[(g + 8) * XCS + hb1] + c3 * m1;
        }
    }
}

extern "C" void kernel_launch(void* const* d_in, const int* in_sizes, int n_in,
                              void* d_out, int out_size)
{
    const float* x  = (const float*)d_in[0];
    const float* w1 = (const float*)d_in[1];
    const float* b1 = (const float*)d_in[2];
    const float* w2 = (const float*)d_in[3];
    const float* b2 = (const float*)d_in[4];
    const float* w3 = (const float*)d_in[5];
    const float* b3 = (const float*)d_in[6];
    const uint32_t* mask = (const uint32_t*)d_in[7];
    float* out = (float*)d_out;

    cudaFuncSetAttribute(nca_step_kernel,
                         cudaFuncAttributeMaxDynamicSharedMemorySize, SMEM_BYTES);
    dim3 grid(HW / TW, HW / TH, 16);
    nca_step_kernel<<<grid, 256, SMEM_BYTES>>>(x, w1, b1, w2, b2, w3, b3, mask, out);
}

// round 12
// speedup vs baseline: 1.2705x; 1.1081x over previous
#include <cuda_runtime.h>
#include <cuda_fp16.h>
#include <stdint.h>

// NCA step via fp16 mma.sync.m16n8k16, warp-standalone chain, 32 px/warp.
// Tile 32x8 = 256 px/CTA (8 warps, each owns one image row of 32 px).
// GEMM1->2->3 in registers via movmatrix; weight smem reads amortized 2x vs R11.
// 59.8 KB smem, 3 CTAs/SM.

#define HW   256
#define CH   16
#define TW   32
#define TH   8
#define NPIX 256
#define YPP  264      // u32 pitch (264 mod 32 == 8 -> B-fragment LDS conflict-free)
#define XCS  340      // fp32 halo channel stride xs[16][10*34]

// u32-unit offsets
#define OFF_YS   0          // 24 pair-rows * 264 = 6336
#define OFF_XS   6336       // fp32 halo: 16*340 = 5440
#define OFF_WF1  11776      // 4*3*32*4 = 1536
#define OFF_WF2  13312      // 2*4*32*4 = 1024
#define OFF_WF3  14336      // 1*2*32*4 = 256
#define OFF_B1   14592
#define OFF_B2   14656
#define OFF_B3   14688
#define OFF_MS   14704
#define SMEM_U32 14960
#define SMEM_BYTES (SMEM_U32 * 4)

static_assert(OFF_XS  == OFF_YS + 24 * YPP, "ys");
static_assert(OFF_WF1 == OFF_XS + 16 * XCS, "xs");
static_assert(OFF_WF2 == OFF_WF1 + 1536, "wf1");
static_assert(OFF_WF3 == OFF_WF2 + 1024, "wf2");
static_assert(OFF_B1  == OFF_WF3 + 256, "wf3");
static_assert(OFF_MS + NPIX == SMEM_U32, "total");
static_assert(3 * SMEM_BYTES <= 227 * 1024, "3 CTA/SM");

__device__ __forceinline__ float tanh_fast(float v) {
    float y;
    asm("tanh.approx.f32 %0, %1;" : "=f"(y) : "f"(v));
    return y;
}
__device__ __forceinline__ uint32_t pack2h(float a, float b) {
    __half2 h = __floats2half2_rn(a, b);       // a -> low half
    return *(uint32_t*)&h;
}
__device__ __forceinline__ uint32_t movm_t(uint32_t s) {
    uint32_t d;
    asm("movmatrix.sync.aligned.m8n8.trans.b16 %0, %1;" : "=r"(d) : "r"(s));
    return d;
}
__device__ __forceinline__ void mma_f16(float& c0, float& c1, float& c2, float& c3,
                                        uint32_t a0, uint32_t a1, uint32_t a2, uint32_t a3,
                                        uint32_t b0, uint32_t b1)
{
    asm volatile(
        "mma.sync.aligned.m16n8k16.row.col.f32.f16.f16.f32 "
        "{%0,%1,%2,%3},{%4,%5,%6,%7},{%8,%9},{%0,%1,%2,%3};"
        : "+f"(c0), "+f"(c1), "+f"(c2), "+f"(c3)
        : "r"(a0), "r"(a1), "r"(a2), "r"(a3), "r"(b0), "r"(b1));
}

// Stage weights [K=KT*16][D] (fp32, d-contiguous) into fragment order.
template<int D, int KT>
__device__ __forceinline__ void stage_w(const float* __restrict__ w, uint32_t* dst, int tid)
{
    #pragma unroll 1
    for (int p = tid; p < 8 * KT * D; p += 256) {
        int kp = p / D, d = p % D;
        int kt = kp >> 3, kl = kp & 7;
        int t = kl & 3, khalf = kl >> 2;
        int dt = d >> 4, g = d & 7, rhi = (d >> 3) & 1;
        int reg = khalf * 2 + rhi, lane = g * 4 + t;
        float lo = w[(2 * kp) * D + d];
        float hi = w[(2 * kp + 1) * D + d];
        dst[((dt * KT + kt) * 32 + lane) * 4 + reg] = pack2h(lo, hi);
    }
}

__global__ __launch_bounds__(256, 3)
void nca_step_kernel(const float* __restrict__ x,
                     const float* __restrict__ w1, const float* __restrict__ b1,
                     const float* __restrict__ w2, const float* __restrict__ b2,
                     const float* __restrict__ w3, const float* __restrict__ b3,
                     const uint32_t* __restrict__ mask,
                     float* __restrict__ out)
{
    extern __shared__ uint32_t smu[];
    uint32_t* ysU = smu + OFF_YS;
    float*    xs  = (float*)(smu + OFF_XS);
    uint32_t* wf1 = smu + OFF_WF1;
    uint32_t* wf2 = smu + OFF_WF2;
    uint32_t* wf3 = smu + OFF_WF3;
    float*    b1s = (float*)(smu + OFF_B1);
    float*    b2s = (float*)(smu + OFF_B2);
    float*    b3s = (float*)(smu + OFF_B3);
    float*    ms  = (float*)(smu + OFF_MS);

    const int tid = threadIdx.x;
    const int bx = blockIdx.x, by = blockIdx.y, bb = blockIdx.z;
    const int y0 = by * TH, x0 = bx * TW;

    // ---------------- phase 0: weight fragments / biases / mask / halo ----------------
    stage_w<64, 3>(w1, wf1, tid);
    stage_w<32, 4>(w2, wf2, tid);
    stage_w<16, 2>(w3, wf3, tid);

    if (tid < 64)       b1s[tid] = b1[tid];
    else if (tid < 96)  b2s[tid - 64] = b2[tid - 64];
    else if (tid < 112) b3s[tid - 96] = b3[tid - 96];

    {   // mask: pixel p = tid (py = tid>>5, xx = tid&31)
        int py = tid >> 5, xx = tid & 31;
        uint32_t w = mask[((size_t)bb * HW + (y0 + py)) * HW + (x0 + xx)];
        ms[tid] = (w != 0u) ? 1.f : 0.f;
    }

    {   // halo 10x34, channel-major fp32, zero-pad outside image
        const float* xb = x + (size_t)bb * HW * HW * CH;
        const int gy0 = y0 - 1, gx0 = x0 - 1;
        for (int i = tid; i < 10 * 34 * 4; i += 256) {
            int q = i & 3, pix = i >> 2;
            int r = pix / 34, cc = pix - r * 34;
            int gr = gy0 + r, gc = gx0 + cc;
            float4 v = make_float4(0.f, 0.f, 0.f, 0.f);
            if ((unsigned)gr < HW && (unsigned)gc < HW)
                v = *(const float4*)&xb[((size_t)gr * HW + gc) * CH + q * 4];
            int base = r * 34 + cc;
            xs[(4 * q + 0) * XCS + base] = v.x;
            xs[(4 * q + 1) * XCS + base] = v.y;
            xs[(4 * q + 2) * XCS + base] = v.z;
            xs[(4 * q + 3) * XCS + base] = v.w;
        }
    }
    __syncthreads();

    // ---------------- phase 1: stencil -> ys (fp16 k-pair packed halves) ----------------
    {
        const int c = tid >> 4, xxh = tid & 15;
        const float* xc = xs + c * XCS;
        __half* ysH = (__half*)ysU;
        const int f0 = 3 * c, f1 = 3 * c + 1, f2 = 3 * c + 2;
        __half* pI = ysH + (f0 >> 1) * (2 * YPP) + (f0 & 1);
        __half* pX = ysH + (f1 >> 1) * (2 * YPP) + (f1 & 1);
        __half* pY = ysH + (f2 >> 1) * (2 * YPP) + (f2 & 1);
        #pragma unroll
        for (int half = 0; half < 2; half++) {
            const int xx = xxh + half * 16;
            float r0a = xc[xx],      r0b = xc[xx + 1],      r0c = xc[xx + 2];
            float r1a = xc[34 + xx], r1b = xc[34 + xx + 1], r1c = xc[34 + xx + 2];
            #pragma unroll
            for (int py = 0; py < TH; py++) {
                const float* row2 = xc + (py + 2) * 34 + xx;
                float r2a = row2[0], r2b = row2[1], r2c = row2[2];
                float gx = ((r0c - r0a) + 2.f * (r1c - r1a) + (r2c - r2a)) * 0.125f;
                float gy = ((r2a - r0a) + 2.f * (r2b - r0b) + (r2c - r0c)) * 0.125f;
                int p2 = (py * 32 + xx) * 2;
                pI[p2] = __float2half_rn(r1b);
                pX[p2] = __float2half_rn(gx);
                pY[p2] = __float2half_rn(gy);
                r0a = r1a; r0b = r1b; r0c = r1c;
                r1a = r2a; r1b = r2b; r1c = r2c;
            }
        }
    }
    __syncthreads();

    // ---------------- warp-standalone GEMM chain: 32 px (one row) per warp ----------------
    const int lane = tid & 31, warp = tid >> 5;
    const int g = lane >> 2, t = lane & 3;
    const int px0 = warp * 32;   // warp owns tile row `warp`

    // GEMM1: h1 = tanh(W1^T @ ys + b1) -> h1B[kt=4][nt=4][2]
    uint32_t h1B[4][4][2];
    {
        uint32_t ysB[3][4][2];
        #pragma unroll
        for (int kt = 0; kt < 3; kt++)
            #pragma unroll
            for (int nt = 0; nt < 4; nt++) {
                ysB[kt][nt][0] = ysU[(8 * kt + t) * YPP + px0 + nt * 8 + g];
                ysB[kt][nt][1] = ysU[(8 * kt + t + 4) * YPP + px0 + nt * 8 + g];
            }
        #pragma unroll
        for (int mt = 0; mt < 4; mt++) {
            uint4 A0 = *(const uint4*)&wf1[((mt * 3 + 0) * 32 + lane) * 4];
            uint4 A1 = *(const uint4*)&wf1[((mt * 3 + 1) * 32 + lane) * 4];
            uint4 A2 = *(const uint4*)&wf1[((mt * 3 + 2) * 32 + lane) * 4];
            const float bl = b1s[mt * 16 + g], bh = b1s[mt * 16 + g + 8];
            #pragma unroll
            for (int nt = 0; nt < 4; nt++) {
                float c0 = bl, c1 = bl, c2 = bh, c3 = bh;
                mma_f16(c0, c1, c2, c3, A0.x, A0.y, A0.z, A0.w, ysB[0][nt][0], ysB[0][nt][1]);
                mma_f16(c0, c1, c2, c3, A1.x, A1.y, A1.z, A1.w, ysB[1][nt][0], ysB[1][nt][1]);
                mma_f16(c0, c1, c2, c3, A2.x, A2.y, A2.z, A2.w, ysB[2][nt][0], ysB[2][nt][1]);
                h1B[mt][nt][0] = movm_t(pack2h(tanh_fast(c0), tanh_fast(c1)));
                h1B[mt][nt][1] = movm_t(pack2h(tanh_fast(c2), tanh_fast(c3)));
            }
        }
    }

    // GEMM2: h2 = tanh(W2^T @ h1 + b2) -> h2B[kt=2][nt=4][2]
    uint32_t h2B[2][4][2];
    #pragma unroll
    for (int mt = 0; mt < 2; mt++) {
        uint4 A0 = *(const uint4*)&wf2[((mt * 4 + 0) * 32 + lane) * 4];
        uint4 A1 = *(const uint4*)&wf2[((mt * 4 + 1) * 32 + lane) * 4];
        uint4 A2 = *(const uint4*)&wf2[((mt * 4 + 2) * 32 + lane) * 4];
        uint4 A3 = *(const uint4*)&wf2[((mt * 4 + 3) * 32 + lane) * 4];
        const float bl = b2s[mt * 16 + g], bh = b2s[mt * 16 + g + 8];
        #pragma unroll
        for (int nt = 0; nt < 4; nt++) {
            float c0 = bl, c1 = bl, c2 = bh, c3 = bh;
            mma_f16(c0, c1, c2, c3, A0.x, A0.y, A0.z, A0.w, h1B[0][nt][0], h1B[0][nt][1]);
            mma_f16(c0, c1, c2, c3, A1.x, A1.y, A1.z, A1.w, h1B[1][nt][0], h1B[1][nt][1]);
            mma_f16(c0, c1, c2, c3, A2.x, A2.y, A2.z, A2.w, h1B[2][nt][0], h1B[2][nt][1]);
            mma_f16(c0, c1, c2, c3, A3.x, A3.y, A3.z, A3.w, h1B[3][nt][0], h1B[3][nt][1]);
            h2B[mt][nt][0] = movm_t(pack2h(tanh_fast(c0), tanh_fast(c1)));
            h2B[mt][nt][1] = movm_t(pack2h(tanh_fast(c2), tanh_fast(c3)));
        }
    }

    // GEMM3: dx = W3^T @ h2 + b3, fused epilogue (out = x + dx*mask)
    {
        uint4 A0 = *(const uint4*)&wf3[(0 * 32 + lane) * 4];
        uint4 A1 = *(const uint4*)&wf3[(1 * 32 + lane) * 4];
        const float bl = b3s[g], bh = b3s[g + 8];
        // warp's image row: y0 + warp
        float* orow = out + (((size_t)bb * HW + (y0 + warp)) * HW + x0) * CH;
        const float* xrow = xs + (warp + 1) * 34;   // + c*XCS + (col+1)
        #pragma unroll
        for (int nt = 0; nt < 4; nt++) {
            float c0 = bl, c1 = bl, c2 = bh, c3 = bh;
            mma_f16(c0, c1, c2, c3, A0.x, A0.y, A0.z, A0.w, h2B[0][nt][0], h2B[0][nt][1]);
            mma_f16(c0, c1, c2, c3, A1.x, A1.y, A1.z, A1.w, h2B[1][nt][0], h2B[1][nt][1]);
            const int col0 = nt * 8 + 2 * t, col1 = col0 + 1;
            const float m0 = ms[px0 + col0], m1 = ms[px0 + col1];
            float* o0 = orow + (size_t)col0 * CH;
            float* o1 = orow + (size_t)col1 * CH;
            o0[g]     = xrow[g * XCS + col0 + 1]       + c0 * m0;
            o1[g]     = xrow[g * XCS + col1 + 1]       + c1 * m1;
            o0[g + 8] = xrow[(g + 8) * XCS + col0 + 1] + c2 * m0;
            o1[g + 8] = xrow[(g + 8) * XCS + col1 + 1] + c3 * m1;
        }
    }
}

extern "C" void kernel_launch(void* const* d_in, const int* in_sizes, int n_in,
                              void* d_out, int out_size)
{
    const float* x  = (const float*)d_in[0];
    const float* w1 = (const float*)d_in[1];
    const float* b1 = (const float*)d_in[2];
    const float* w2 = (const float*)d_in[3];
    const float* b2 = (const float*)d_in[4];
    const float* w3 = (const float*)d_in[5];
    const float* b3 = (const float*)d_in[6];
    const uint32_t* mask = (const uint32_t*)d_in[7];
    float* out = (float*)d_out;

    cudaFuncSetAttribute(nca_step_kernel,
                         cudaFuncAttributeMaxDynamicSharedMemorySize, SMEM_BYTES);
    dim3 grid(HW / TW, HW / TH, 16);
    nca_step_kernel<<<grid, 256, SMEM_BYTES>>>(x, w1, b1, w2, b2, w3, b3, mask, out);
}

// round 13
// speedup vs baseline: 1.3684x; 1.0771x over previous
#include <cuda_runtime.h>
#include <cuda_fp16.h>
#include <stdint.h>

// NCA step via fp16 mma.sync.m16n8k16, warp-standalone chain, 32 px/warp.
// R13: fp16 half2 halo + half2 stencil (warp=channel-pair, lane=column);
// epilogue x re-read from gmem (L2-hot). 47.8 KB smem, 3 CTAs/SM.

#define HW   256
#define CH   16
#define TW   32
#define TH   8
#define NPIX 256
#define YPP  264      // u32 pitch for packed ys rows (conflict-free B-fragment LDS)
#define XC2  340      // u32 pitch for fp16 halo rows xh[8][10*34]

// u32-unit offsets
#define OFF_YS   0          // 24 pair-rows * 264 = 6336
#define OFF_XH   6336       // 8 * 340 = 2720
#define OFF_WF1  9056       // 1536
#define OFF_WF2  10592      // 1024
#define OFF_WF3  11616      // 256
#define OFF_B1   11872
#define OFF_B2   11936
#define OFF_B3   11968
#define OFF_MS   11984
#define SMEM_U32 12240
#define SMEM_BYTES (SMEM_U32 * 4)

static_assert(OFF_XH  == OFF_YS + 24 * YPP, "ys");
static_assert(OFF_WF1 == OFF_XH + 8 * XC2, "xh");
static_assert(OFF_WF2 == OFF_WF1 + 1536, "wf1");
static_assert(OFF_WF3 == OFF_WF2 + 1024, "wf2");
static_assert(OFF_B1  == OFF_WF3 + 256, "wf3");
static_assert(OFF_MS + NPIX == SMEM_U32, "total");
static_assert(3 * SMEM_BYTES <= 227 * 1024, "3 CTA/SM");

__device__ __forceinline__ float tanh_fast(float v) {
    float y;
    asm("tanh.approx.f32 %0, %1;" : "=f"(y) : "f"(v));
    return y;
}
__device__ __forceinline__ uint32_t pack2h(float a, float b) {
    __half2 h = __floats2half2_rn(a, b);       // a -> low half
    return *(uint32_t*)&h;
}
__device__ __forceinline__ uint32_t movm_t(uint32_t s) {
    uint32_t d;
    asm("movmatrix.sync.aligned.m8n8.trans.b16 %0, %1;" : "=r"(d) : "r"(s));
    return d;
}
__device__ __forceinline__ void mma_f16(float& c0, float& c1, float& c2, float& c3,
                                        uint32_t a0, uint32_t a1, uint32_t a2, uint32_t a3,
                                        uint32_t b0, uint32_t b1)
{
    asm volatile(
        "mma.sync.aligned.m16n8k16.row.col.f32.f16.f16.f32 "
        "{%0,%1,%2,%3},{%4,%5,%6,%7},{%8,%9},{%0,%1,%2,%3};"
        : "+f"(c0), "+f"(c1), "+f"(c2), "+f"(c3)
        : "r"(a0), "r"(a1), "r"(a2), "r"(a3), "r"(b0), "r"(b1));
}

// Stage weights [K=KT*16][D] (fp32, d-contiguous) into fragment order.
template<int D, int KT>
__device__ __forceinline__ void stage_w(const float* __restrict__ w, uint32_t* dst, int tid)
{
    #pragma unroll 1
    for (int p = tid; p < 8 * KT * D; p += 256) {
        int kp = p / D, d = p % D;
        int kt = kp >> 3, kl = kp & 7;
        int t = kl & 3, khalf = kl >> 2;
        int dt = d >> 4, g = d & 7, rhi = (d >> 3) & 1;
        int reg = khalf * 2 + rhi, lane = g * 4 + t;
        float lo = w[(2 * kp) * D + d];
        float hi = w[(2 * kp + 1) * D + d];
        dst[((dt * KT + kt) * 32 + lane) * 4 + reg] = pack2h(lo, hi);
    }
}

__global__ __launch_bounds__(256, 3)
void nca_step_kernel(const float* __restrict__ x,
                     const float* __restrict__ w1, const float* __restrict__ b1,
                     const float* __restrict__ w2, const float* __restrict__ b2,
                     const float* __restrict__ w3, const float* __restrict__ b3,
                     const uint32_t* __restrict__ mask,
                     float* __restrict__ out)
{
    extern __shared__ uint32_t smu[];
    uint32_t* ysU = smu + OFF_YS;
    uint32_t* xh  = smu + OFF_XH;
    uint32_t* wf1 = smu + OFF_WF1;
    uint32_t* wf2 = smu + OFF_WF2;
    uint32_t* wf3 = smu + OFF_WF3;
    float*    b1s = (float*)(smu + OFF_B1);
    float*    b2s = (float*)(smu + OFF_B2);
    float*    b3s = (float*)(smu + OFF_B3);
    float*    ms  = (float*)(smu + OFF_MS);

    const int tid = threadIdx.x;
    const int bx = blockIdx.x, by = blockIdx.y, bb = blockIdx.z;
    const int y0 = by * TH, x0 = bx * TW;

    // ---------------- phase 0: weight fragments / biases / mask / fp16 halo ----------------
    stage_w<64, 3>(w1, wf1, tid);
    stage_w<32, 4>(w2, wf2, tid);
    stage_w<16, 2>(w3, wf3, tid);

    if (tid < 64)       b1s[tid] = b1[tid];
    else if (tid < 96)  b2s[tid - 64] = b2[tid - 64];
    else if (tid < 112) b3s[tid - 96] = b3[tid - 96];

    {   // mask: pixel p = tid (py = tid>>5, xx = tid&31)
        int py = tid >> 5, xx = tid & 31;
        uint32_t w = mask[((size_t)bb * HW + (y0 + py)) * HW + (x0 + xx)];
        ms[tid] = (w != 0u) ? 1.f : 0.f;
    }

    {   // halo 10x34, fp16 channel-pair packed: xh[cp][r*34+cc], zero-pad outside
        const float* xb = x + (size_t)bb * HW * HW * CH;
        const int gy0 = y0 - 1, gx0 = x0 - 1;
        for (int i = tid; i < 10 * 34 * 4; i += 256) {
            int q = i & 3, pix = i >> 2;
            int r = pix / 34, cc = pix - r * 34;
            int gr = gy0 + r, gc = gx0 + cc;
            float4 v = make_float4(0.f, 0.f, 0.f, 0.f);
            if ((unsigned)gr < HW && (unsigned)gc < HW)
                v = *(const float4*)&xb[((size_t)gr * HW + gc) * CH + q * 4];
            int base = r * 34 + cc;
            xh[(2 * q + 0) * XC2 + base] = pack2h(v.x, v.y);
            xh[(2 * q + 1) * XC2 + base] = pack2h(v.z, v.w);
        }
    }
    __syncthreads();

    const int lane = tid & 31, warp = tid >> 5;

    // ---------------- phase 1: half2 stencil -> ys (warp = channel pair, lane = column) ----------------
    {
        const __half2* xc = (const __half2*)(xh + warp * XC2);
        const int xx = lane;
        const __half2 two    = __floats2half2_rn(2.f, 2.f);
        const __half2 eighth = __floats2half2_rn(0.125f, 0.125f);
        __half2 r0a = xc[xx],      r0b = xc[xx + 1],      r0c = xc[xx + 2];
        __half2 r1a = xc[34 + xx], r1b = xc[34 + xx + 1], r1c = xc[34 + xx + 2];
        const int m = warp;   // channel pair index
        #pragma unroll
        for (int py = 0; py < TH; py++) {
            const __half2* row2 = xc + (py + 2) * 34 + xx;
            __half2 r2a = row2[0], r2b = row2[1], r2c = row2[2];
            __half2 gx2 = __hmul2(__hadd2(__hadd2(__hsub2(r0c, r0a), __hsub2(r2c, r2a)),
                                          __hmul2(two, __hsub2(r1c, r1a))), eighth);
            __half2 gy2 = __hmul2(__hadd2(__hadd2(__hsub2(r2a, r0a), __hsub2(r2c, r0c)),
                                          __hmul2(two, __hsub2(r2b, r0b))), eighth);
            uint32_t I2u  = *(uint32_t*)&r1b;
            uint32_t gx2u = *(uint32_t*)&gx2;
            uint32_t gy2u = *(uint32_t*)&gy2;
            int p = py * 32 + xx;
            ysU[(3 * m + 0) * YPP + p] = __byte_perm(I2u,  gx2u, 0x5410);  // (I_e , gx_e)
            ysU[(3 * m + 1) * YPP + p] = __byte_perm(gy2u, I2u,  0x7610);  // (gy_e, I_o )
            ysU[(3 * m + 2) * YPP + p] = __byte_perm(gx2u, gy2u, 0x7632);  // (gx_o, gy_o)
            r0a = r1a; r0b = r1b; r0c = r1c;
            r1a = r2a; r1b = r2b; r1c = r2c;
        }
    }
    __syncthreads();

    // ---------------- warp-standalone GEMM chain: 32 px (one row) per warp ----------------
    const int g = lane >> 2, t = lane & 3;
    const int px0 = warp * 32;

    // GEMM1: h1 = tanh(W1^T @ ys + b1) -> h1B[kt=4][nt=4][2]
    uint32_t h1B[4][4][2];
    {
        uint32_t ysB[3][4][2];
        #pragma unroll
        for (int kt = 0; kt < 3; kt++)
            #pragma unroll
            for (int nt = 0; nt < 4; nt++) {
                ysB[kt][nt][0] = ysU[(8 * kt + t) * YPP + px0 + nt * 8 + g];
                ysB[kt][nt][1] = ysU[(8 * kt + t + 4) * YPP + px0 + nt * 8 + g];
            }
        #pragma unroll
        for (int mt = 0; mt < 4; mt++) {
            uint4 A0 = *(const uint4*)&wf1[((mt * 3 + 0) * 32 + lane) * 4];
            uint4 A1 = *(const uint4*)&wf1[((mt * 3 + 1) * 32 + lane) * 4];
            uint4 A2 = *(const uint4*)&wf1[((mt * 3 + 2) * 32 + lane) * 4];
            const float bl = b1s[mt * 16 + g], bh = b1s[mt * 16 + g + 8];
            #pragma unroll
            for (int nt = 0; nt < 4; nt++) {
                float c0 = bl, c1 = bl, c2 = bh, c3 = bh;
                mma_f16(c0, c1, c2, c3, A0.x, A0.y, A0.z, A0.w, ysB[0][nt][0], ysB[0][nt][1]);
                mma_f16(c0, c1, c2, c3, A1.x, A1.y, A1.z, A1.w, ysB[1][nt][0], ysB[1][nt][1]);
                mma_f16(c0, c1, c2, c3, A2.x, A2.y, A2.z, A2.w, ysB[2][nt][0], ysB[2][nt][1]);
                h1B[mt][nt][0] = movm_t(pack2h(tanh_fast(c0), tanh_fast(c1)));
                h1B[mt][nt][1] = movm_t(pack2h(tanh_fast(c2), tanh_fast(c3)));
            }
        }
    }

    // GEMM2: h2 = tanh(W2^T @ h1 + b2) -> h2B[kt=2][nt=4][2]
    uint32_t h2B[2][4][2];
    #pragma unroll
    for (int mt = 0; mt < 2; mt++) {
        uint4 A0 = *(const uint4*)&wf2[((mt * 4 + 0) * 32 + lane) * 4];
        uint4 A1 = *(const uint4*)&wf2[((mt * 4 + 1) * 32 + lane) * 4];
        uint4 A2 = *(const uint4*)&wf2[((mt * 4 + 2) * 32 + lane) * 4];
        uint4 A3 = *(const uint4*)&wf2[((mt * 4 + 3) * 32 + lane) * 4];
        const float bl = b2s[mt * 16 + g], bh = b2s[mt * 16 + g + 8];
        #pragma unroll
        for (int nt = 0; nt < 4; nt++) {
            float c0 = bl, c1 = bl, c2 = bh, c3 = bh;
            mma_f16(c0, c1, c2, c3, A0.x, A0.y, A0.z, A0.w, h1B[0][nt][0], h1B[0][nt][1]);
            mma_f16(c0, c1, c2, c3, A1.x, A1.y, A1.z, A1.w, h1B[1][nt][0], h1B[1][nt][1]);
            mma_f16(c0, c1, c2, c3, A2.x, A2.y, A2.z, A2.w, h1B[2][nt][0], h1B[2][nt][1]);
            mma_f16(c0, c1, c2, c3, A3.x, A3.y, A3.z, A3.w, h1B[3][nt][0], h1B[3][nt][1]);
            h2B[mt][nt][0] = movm_t(pack2h(tanh_fast(c0), tanh_fast(c1)));
            h2B[mt][nt][1] = movm_t(pack2h(tanh_fast(c2), tanh_fast(c3)));
        }
    }

    // GEMM3: dx = W3^T @ h2 + b3, fused epilogue (out = x + dx*mask, x from gmem)
    {
        uint4 A0 = *(const uint4*)&wf3[(0 * 32 + lane) * 4];
        uint4 A1 = *(const uint4*)&wf3[(1 * 32 + lane) * 4];
        const float bl = b3s[g], bh = b3s[g + 8];
        const size_t rowoff = (((size_t)bb * HW + (y0 + warp)) * HW + x0) * CH;
        float* orow = out + rowoff;
        const float* xrow = x + rowoff;
        #pragma unroll
        for (int nt = 0; nt < 4; nt++) {
            float c0 = bl, c1 = bl, c2 = bh, c3 = bh;
            mma_f16(c0, c1, c2, c3, A0.x, A0.y, A0.z, A0.w, h2B[0][nt][0], h2B[0][nt][1]);
            mma_f16(c0, c1, c2, c3, A1.x, A1.y, A1.z, A1.w, h2B[1][nt][0], h2B[1][nt][1]);
            const int col0 = nt * 8 + 2 * t, col1 = col0 + 1;
            const float m0 = ms[px0 + col0], m1 = ms[px0 + col1];
            float* o0 = orow + (size_t)col0 * CH;
            float* o1 = orow + (size_t)col1 * CH;
            const float* xg0 = xrow + (size_t)col0 * CH;
            const float* xg1 = xrow + (size_t)col1 * CH;
            o0[g]     = xg0[g]     + c0 * m0;
            o1[g]     = xg1[g]     + c1 * m1;
            o0[g + 8] = xg0[g + 8] + c2 * m0;
            o1[g + 8] = xg1[g + 8] + c3 * m1;
        }
    }
}

extern "C" void kernel_launch(void* const* d_in, const int* in_sizes, int n_in,
                              void* d_out, int out_size)
{
    const float* x  = (const float*)d_in[0];
    const float* w1 = (const float*)d_in[1];
    const float* b1 = (const float*)d_in[2];
    const float* w2 = (const float*)d_in[3];
    const float* b2 = (const float*)d_in[4];
    const float* w3 = (const float*)d_in[5];
    const float* b3 = (const float*)d_in[6];
    const uint32_t* mask = (const uint32_t*)d_in[7];
    float* out = (float*)d_out;

    cudaFuncSetAttribute(nca_step_kernel,
                         cudaFuncAttributeMaxDynamicSharedMemorySize, SMEM_BYTES);
    dim3 grid(HW / TW, HW / TH, 16);
    nca_step_kernel<<<grid, 256, SMEM_BYTES>>>(x, w1, b1, w2, b2, w3, b3, mask, out);
}

// round 14
// speedup vs baseline: 1.4379x; 1.0507x over previous
#include <cuda_runtime.h>
#include <cuda_fp16.h>
#include <stdint.h>

// NCA step via fp16 mma.sync.m16n8k16, warp-standalone chain, 32 px/warp.
// R14: chain split into two 16-px passes -> register peak ~62 -> 4 CTAs/SM.
// fp16 half2 halo + stencil; epilogue x re-read from gmem. 47.8 KB smem.

#define HW   256
#define CH   16
#define TW   32
#define TH   8
#define NPIX 256
#define YPP  264      // u32 pitch for packed ys rows (conflict-free B-fragment LDS)
#define XC2  340      // u32 pitch for fp16 halo rows xh[8][10*34]

// u32-unit offsets
#define OFF_YS   0          // 24 pair-rows * 264 = 6336
#define OFF_XH   6336       // 8 * 340 = 2720
#define OFF_WF1  9056       // 1536
#define OFF_WF2  10592      // 1024
#define OFF_WF3  11616      // 256
#define OFF_B1   11872
#define OFF_B2   11936
#define OFF_B3   11968
#define OFF_MS   11984
#define SMEM_U32 12240
#define SMEM_BYTES (SMEM_U32 * 4)

static_assert(OFF_XH  == OFF_YS + 24 * YPP, "ys");
static_assert(OFF_WF1 == OFF_XH + 8 * XC2, "xh");
static_assert(OFF_WF2 == OFF_WF1 + 1536, "wf1");
static_assert(OFF_WF3 == OFF_WF2 + 1024, "wf2");
static_assert(OFF_B1  == OFF_WF3 + 256, "wf3");
static_assert(OFF_MS + NPIX == SMEM_U32, "total");
static_assert(4 * SMEM_BYTES <= 227 * 1024, "4 CTA/SM smem");

__device__ __forceinline__ float tanh_fast(float v) {
    float y;
    asm("tanh.approx.f32 %0, %1;" : "=f"(y) : "f"(v));
    return y;
}
__device__ __forceinline__ uint32_t pack2h(float a, float b) {
    __half2 h = __floats2half2_rn(a, b);       // a -> low half
    return *(uint32_t*)&h;
}
__device__ __forceinline__ uint32_t movm_t(uint32_t s) {
    uint32_t d;
    asm("movmatrix.sync.aligned.m8n8.trans.b16 %0, %1;" : "=r"(d) : "r"(s));
    return d;
}
__device__ __forceinline__ void mma_f16(float& c0, float& c1, float& c2, float& c3,
                                        uint32_t a0, uint32_t a1, uint32_t a2, uint32_t a3,
                                        uint32_t b0, uint32_t b1)
{
    asm volatile(
        "mma.sync.aligned.m16n8k16.row.col.f32.f16.f16.f32 "
        "{%0,%1,%2,%3},{%4,%5,%6,%7},{%8,%9},{%0,%1,%2,%3};"
        : "+f"(c0), "+f"(c1), "+f"(c2), "+f"(c3)
        : "r"(a0), "r"(a1), "r"(a2), "r"(a3), "r"(b0), "r"(b1));
}

// Stage weights [K=KT*16][D] (fp32, d-contiguous) into fragment order.
template<int D, int KT>
__device__ __forceinline__ void stage_w(const float* __restrict__ w, uint32_t* dst, int tid)
{
    #pragma unroll 1
    for (int p = tid; p < 8 * KT * D; p += 256) {
        int kp = p / D, d = p % D;
        int kt = kp >> 3, kl = kp & 7;
        int t = kl & 3, khalf = kl >> 2;
        int dt = d >> 4, g = d & 7, rhi = (d >> 3) & 1;
        int reg = khalf * 2 + rhi, lane = g * 4 + t;
        float lo = w[(2 * kp) * D + d];
        float hi = w[(2 * kp + 1) * D + d];
        dst[((dt * KT + kt) * 32 + lane) * 4 + reg] = pack2h(lo, hi);
    }
}

__global__ __launch_bounds__(256, 4)
void nca_step_kernel(const float* __restrict__ x,
                     const float* __restrict__ w1, const float* __restrict__ b1,
                     const float* __restrict__ w2, const float* __restrict__ b2,
                     const float* __restrict__ w3, const float* __restrict__ b3,
                     const uint32_t* __restrict__ mask,
                     float* __restrict__ out)
{
    extern __shared__ uint32_t smu[];
    uint32_t* ysU = smu + OFF_YS;
    uint32_t* xh  = smu + OFF_XH;
    uint32_t* wf1 = smu + OFF_WF1;
    uint32_t* wf2 = smu + OFF_WF2;
    uint32_t* wf3 = smu + OFF_WF3;
    float*    b1s = (float*)(smu + OFF_B1);
    float*    b2s = (float*)(smu + OFF_B2);
    float*    b3s = (float*)(smu + OFF_B3);
    float*    ms  = (float*)(smu + OFF_MS);

    const int tid = threadIdx.x;
    const int bx = blockIdx.x, by = blockIdx.y, bb = blockIdx.z;
    const int y0 = by * TH, x0 = bx * TW;

    // ---------------- phase 0: weight fragments / biases / mask / fp16 halo ----------------
    stage_w<64, 3>(w1, wf1, tid);
    stage_w<32, 4>(w2, wf2, tid);
    stage_w<16, 2>(w3, wf3, tid);

    if (tid < 64)       b1s[tid] = b1[tid];
    else if (tid < 96)  b2s[tid - 64] = b2[tid - 64];
    else if (tid < 112) b3s[tid - 96] = b3[tid - 96];

    {   // mask: pixel p = tid (py = tid>>5, xx = tid&31)
        int py = tid >> 5, xx = tid & 31;
        uint32_t w = mask[((size_t)bb * HW + (y0 + py)) * HW + (x0 + xx)];
        ms[tid] = (w != 0u) ? 1.f : 0.f;
    }

    {   // halo 10x34, fp16 channel-pair packed: xh[cp][r*34+cc], zero-pad outside
        const float* xb = x + (size_t)bb * HW * HW * CH;
        const int gy0 = y0 - 1, gx0 = x0 - 1;
        for (int i = tid; i < 10 * 34 * 4; i += 256) {
            int q = i & 3, pix = i >> 2;
            int r = pix / 34, cc = pix - r * 34;
            int gr = gy0 + r, gc = gx0 + cc;
            float4 v = make_float4(0.f, 0.f, 0.f, 0.f);
            if ((unsigned)gr < HW && (unsigned)gc < HW)
                v = *(const float4*)&xb[((size_t)gr * HW + gc) * CH + q * 4];
            int base = r * 34 + cc;
            xh[(2 * q + 0) * XC2 + base] = pack2h(v.x, v.y);
            xh[(2 * q + 1) * XC2 + base] = pack2h(v.z, v.w);
        }
    }
    __syncthreads();

    const int lane = tid & 31, warp = tid >> 5;

    // ---------------- phase 1: half2 stencil -> ys (warp = channel pair, lane = column) ----------------
    {
        const __half2* xc = (const __half2*)(xh + warp * XC2);
        const int xx = lane;
        const __half2 two    = __floats2half2_rn(2.f, 2.f);
        const __half2 eighth = __floats2half2_rn(0.125f, 0.125f);
        __half2 r0a = xc[xx],      r0b = xc[xx + 1],      r0c = xc[xx + 2];
        __half2 r1a = xc[34 + xx], r1b = xc[34 + xx + 1], r1c = xc[34 + xx + 2];
        const int m = warp;   // channel pair index
        #pragma unroll
        for (int py = 0; py < TH; py++) {
            const __half2* row2 = xc + (py + 2) * 34 + xx;
            __half2 r2a = row2[0], r2b = row2[1], r2c = row2[2];
            __half2 gx2 = __hmul2(__hadd2(__hadd2(__hsub2(r0c, r0a), __hsub2(r2c, r2a)),
                                          __hmul2(two, __hsub2(r1c, r1a))), eighth);
            __half2 gy2 = __hmul2(__hadd2(__hadd2(__hsub2(r2a, r0a), __hsub2(r2c, r0c)),
                                          __hmul2(two, __hsub2(r2b, r0b))), eighth);
            uint32_t I2u  = *(uint32_t*)&r1b;
            uint32_t gx2u = *(uint32_t*)&gx2;
            uint32_t gy2u = *(uint32_t*)&gy2;
            int p = py * 32 + xx;
            ysU[(3 * m + 0) * YPP + p] = __byte_perm(I2u,  gx2u, 0x5410);  // (I_e , gx_e)
            ysU[(3 * m + 1) * YPP + p] = __byte_perm(gy2u, I2u,  0x7610);  // (gy_e, I_o )
            ysU[(3 * m + 2) * YPP + p] = __byte_perm(gx2u, gy2u, 0x7632);  // (gx_o, gy_o)
            r0a = r1a; r0b = r1b; r0c = r1c;
            r1a = r2a; r1b = r2b; r1c = r2c;
        }
    }
    __syncthreads();

    // ---------------- warp-standalone GEMM chain: 32 px per warp, 2 passes of 16 px ----------------
    const int g = lane >> 2, t = lane & 3;
    const int px0 = warp * 32;
    const size_t rowoff = (((size_t)bb * HW + (y0 + warp)) * HW + x0) * CH;
    float* orow = out + rowoff;
    const float* xrow = x + rowoff;

    #pragma unroll
    for (int half = 0; half < 2; half++) {
        const int pxh = px0 + half * 16;

        // GEMM1: h1 = tanh(W1^T @ ys + b1) -> h1B[kt=4][nt=2][2]
        uint32_t h1B[4][2][2];
        {
            uint32_t ysB[3][2][2];
            #pragma unroll
            for (int kt = 0; kt < 3; kt++)
                #pragma unroll
                for (int nt = 0; nt < 2; nt++) {
                    ysB[kt][nt][0] = ysU[(8 * kt + t) * YPP + pxh + nt * 8 + g];
                    ysB[kt][nt][1] = ysU[(8 * kt + t + 4) * YPP + pxh + nt * 8 + g];
                }
            #pragma unroll
            for (int mt = 0; mt < 4; mt++) {
                uint4 A0 = *(const uint4*)&wf1[((mt * 3 + 0) * 32 + lane) * 4];
                uint4 A1 = *(const uint4*)&wf1[((mt * 3 + 1) * 32 + lane) * 4];
                uint4 A2 = *(const uint4*)&wf1[((mt * 3 + 2) * 32 + lane) * 4];
                const float bl = b1s[mt * 16 + g], bh = b1s[mt * 16 + g + 8];
                #pragma unroll
                for (int nt = 0; nt < 2; nt++) {
                    float c0 = bl, c1 = bl, c2 = bh, c3 = bh;
                    mma_f16(c0, c1, c2, c3, A0.x, A0.y, A0.z, A0.w, ysB[0][nt][0], ysB[0][nt][1]);
                    mma_f16(c0, c1, c2, c3, A1.x, A1.y, A1.z, A1.w, ysB[1][nt][0], ysB[1][nt][1]);
                    mma_f16(c0, c1, c2, c3, A2.x, A2.y, A2.z, A2.w, ysB[2][nt][0], ysB[2][nt][1]);
                    h1B[mt][nt][0] = movm_t(pack2h(tanh_fast(c0), tanh_fast(c1)));
                    h1B[mt][nt][1] = movm_t(pack2h(tanh_fast(c2), tanh_fast(c3)));
                }
            }
        }

        // GEMM2: h2 = tanh(W2^T @ h1 + b2) -> h2B[kt=2][nt=2][2]
        uint32_t h2B[2][2][2];
        #pragma unroll
        for (int mt = 0; mt < 2; mt++) {
            uint4 A0 = *(const uint4*)&wf2[((mt * 4 + 0) * 32 + lane) * 4];
            uint4 A1 = *(const uint4*)&wf2[((mt * 4 + 1) * 32 + lane) * 4];
            uint4 A2 = *(const uint4*)&wf2[((mt * 4 + 2) * 32 + lane) * 4];
            uint4 A3 = *(const uint4*)&wf2[((mt * 4 + 3) * 32 + lane) * 4];
            const float bl = b2s[mt * 16 + g], bh = b2s[mt * 16 + g + 8];
            #pragma unroll
            for (int nt = 0; nt < 2; nt++) {
                float c0 = bl, c1 = bl, c2 = bh, c3 = bh;
                mma_f16(c0, c1, c2, c3, A0.x, A0.y, A0.z, A0.w, h1B[0][nt][0], h1B[0][nt][1]);
                mma_f16(c0, c1, c2, c3, A1.x, A1.y, A1.z, A1.w, h1B[1][nt][0], h1B[1][nt][1]);
                mma_f16(c0, c1, c2, c3, A2.x, A2.y, A2.z, A2.w, h1B[2][nt][0], h1B[2][nt][1]);
                mma_f16(c0, c1, c2, c3, A3.x, A3.y, A3.z, A3.w, h1B[3][nt][0], h1B[3][nt][1]);
                h2B[mt][nt][0] = movm_t(pack2h(tanh_fast(c0), tanh_fast(c1)));
                h2B[mt][nt][1] = movm_t(pack2h(tanh_fast(c2), tanh_fast(c3)));
            }
        }

        // GEMM3: dx = W3^T @ h2 + b3, fused epilogue (out = x + dx*mask, x from gmem)
        {
            uint4 A0 = *(const uint4*)&wf3[(0 * 32 + lane) * 4];
            uint4 A1 = *(const uint4*)&wf3[(1 * 32 + lane) * 4];
            const float bl = b3s[g], bh = b3s[g + 8];
            #pragma unroll
            for (int nt = 0; nt < 2; nt++) {
                float c0 = bl, c1 = bl, c2 = bh, c3 = bh;
                mma_f16(c0, c1, c2, c3, A0.x, A0.y, A0.z, A0.w, h2B[0][nt][0], h2B[0][nt][1]);
                mma_f16(c0, c1, c2, c3, A1.x, A1.y, A1.z, A1.w, h2B[1][nt][0], h2B[1][nt][1]);
                const int col0 = half * 16 + nt * 8 + 2 * t, col1 = col0 + 1;
                const float m0 = ms[px0 - px0 + half * 16 + nt * 8 + 2 * t + warp * 32], m1 = ms[warp * 32 + half * 16 + nt * 8 + 2 * t + 1];
                float* o0 = orow + (size_t)col0 * CH;
                float* o1 = orow + (size_t)col1 * CH;
                const float* xg0 = xrow + (size_t)col0 * CH;
                const float* xg1 = xrow + (size_t)col1 * CH;
                o0[g]     = xg0[g]     + c0 * m0;
                o1[g]     = xg1[g]     + c1 * m1;
                o0[g + 8] = xg0[g + 8] + c2 * m0;
                o1[g + 8] = xg1[g + 8] + c3 * m1;
            }
        }
    }
}

extern "C" void kernel_launch(void* const* d_in, const int* in_sizes, int n_in,
                              void* d_out, int out_size)
{
    const float* x  = (const float*)d_in[0];
    const float* w1 = (const float*)d_in[1];
    const float* b1 = (const float*)d_in[2];
    const float* w2 = (const float*)d_in[3];
    const float* b2 = (const float*)d_in[4];
    const float* w3 = (const float*)d_in[5];
    const float* b3 = (const float*)d_in[6];
    const uint32_t* mask = (const uint32_t*)d_in[7];
    float* out = (float*)d_out;

    cudaFuncSetAttribute(nca_step_kernel,
                         cudaFuncAttributeMaxDynamicSharedMemorySize, SMEM_BYTES);
    dim3 grid(HW / TW, HW / TH, 16);
    nca_step_kernel<<<grid, 256, SMEM_BYTES>>>(x, w1, b1, w2, b2, w3, b3, mask, out);
}